// round 15
// baseline (speedup 1.0000x reference)
#include <cuda_runtime.h>
#include <cuda_fp16.h>
#include <cstdint>

#define N 8192

// -------------------- device scratch ---------------------------------------
__device__ float g_xqm[N * 64];
__device__ float g_xqv[N * 96];
__device__ float g_qnm[N], g_qnv[N];
__device__ __align__(16) float g_Xnm[N];
__device__ __align__(16) float g_Xnv[N];
__device__ float g_LpA0[N * 32], g_LpB0[N * 32];   // Lambda partials (k-halves)
__device__ float g_LpA1[N * 32], g_LpB1[N * 32];
__device__ float g_zm[N * 32], g_zv[N * 32];
__device__ __align__(16) __half g_Xmh[N * 64];          // X hi (phase1 hi-only)
__device__ __align__(16) __half g_Xvh[N * 96];
__device__ __align__(16) __half g_Lth0[32 * N];         // Lambda^T hi only
__device__ __align__(16) __half g_Lth1[32 * N];
__device__ __align__(16) __half g_Zth0[32 * N];         // Z^T hi only
__device__ __align__(16) __half g_Zth1[32 * N];

// -------------------- mma / ldmatrix / cp.async helpers ---------------------
__device__ __forceinline__ void mma_f16(float c[4], const uint32_t a[4],
                                        uint32_t b0, uint32_t b1) {
    asm volatile(
        "mma.sync.aligned.m16n8k16.row.col.f32.f16.f16.f32 "
        "{%0,%1,%2,%3}, {%4,%5,%6,%7}, {%8,%9}, {%0,%1,%2,%3};"
        : "+f"(c[0]), "+f"(c[1]), "+f"(c[2]), "+f"(c[3])
        : "r"(a[0]), "r"(a[1]), "r"(a[2]), "r"(a[3]), "r"(b0), "r"(b1));
}
__device__ __forceinline__ uint32_t packhf(float lo, float hi) {
    uint32_t r;
    asm("cvt.rn.f16x2.f32 %0, %1, %2;" : "=r"(r) : "f"(hi), "f"(lo));
    return r;
}
__device__ __forceinline__ uint32_t s2u(const void* p) {
    return (uint32_t)__cvta_generic_to_shared(p);
}
__device__ __forceinline__ void ldsm4(uint32_t* r, uint32_t addr) {
    asm volatile("ldmatrix.sync.aligned.m8n8.x4.shared.b16 {%0,%1,%2,%3}, [%4];"
                 : "=r"(r[0]), "=r"(r[1]), "=r"(r[2]), "=r"(r[3]) : "r"(addr));
}
__device__ __forceinline__ void cpasync16(uint32_t dst, const void* src) {
    asm volatile("cp.async.cg.shared.global [%0], [%1], 16;"
                 :: "r"(dst), "l"(src) : "memory");
}
#define CP_COMMIT() asm volatile("cp.async.commit_group;" ::: "memory")
#define CP_WAIT1()  asm volatile("cp.async.wait_group 1;" ::: "memory")
// group-scoped named barrier: 256 threads of group g
#define GBAR(g) asm volatile("bar.sync %0, 256;" :: "r"(1 + (g)) : "memory")

// -------------------- merged prep kernel ------------------------------------
// blocks 0..1023: build query features + |q|^2
// blocks 1024..2047: X fp16 + |X|^2
// blocks 2048..4095: Z -> transposed fp16 hi
__global__ void prep_all_kernel(const float* __restrict__ x_mu,
                                const float* __restrict__ y_eta,
                                const float* __restrict__ y_mean,
                                const float* __restrict__ y_var,
                                const float* __restrict__ Xm,
                                const float* __restrict__ Xv,
                                const float* __restrict__ Z0,
                                const float* __restrict__ Z1) {
    int b = blockIdx.x;
    int tid = threadIdx.x;
    if (b < 1024) {
        int q = (b * 256 + tid) >> 5;
        int lane = tid & 31;
        float a = x_mu[q * 32 + lane];
        float m = y_mean[q * 32 + lane] + y_var[q * 32 + lane];
        float e = 0.01f * y_eta[(N - 1 - q) * 32 + lane];
        g_xqm[q * 64 + lane] = a;       g_xqm[q * 64 + 32 + lane] = m;
        g_xqv[q * 96 + lane] = a;       g_xqv[q * 96 + 32 + lane] = e;
        g_xqv[q * 96 + 64 + lane] = m;
        float nm = a * a + m * m, nv = nm + e * e;
        #pragma unroll
        for (int o = 16; o; o >>= 1) {
            nm += __shfl_xor_sync(0xffffffffu, nm, o);
            nv += __shfl_xor_sync(0xffffffffu, nv, o);
        }
        if (lane == 0) { g_qnm[q] = nm; g_qnv[q] = nv; }
    } else if (b < 2048) {
        int i = ((b - 1024) * 256 + tid) >> 5;
        int lane = tid & 31;
        float nm = 0.f, nv = 0.f;
        #pragma unroll
        for (int c = 0; c < 64; c += 32) {
            float v = Xm[(size_t)i * 64 + c + lane];
            nm += v * v;
            g_Xmh[(size_t)i * 64 + c + lane] = __float2half_rn(v);
        }
        #pragma unroll
        for (int c = 0; c < 96; c += 32) {
            float v = Xv[(size_t)i * 96 + c + lane];
            nv += v * v;
            g_Xvh[(size_t)i * 96 + c + lane] = __float2half_rn(v);
        }
        #pragma unroll
        for (int o = 16; o; o >>= 1) {
            nm += __shfl_xor_sync(0xffffffffu, nm, o);
            nv += __shfl_xor_sync(0xffffffffu, nv, o);
        }
        if (lane == 0) { g_Xnm[i] = nm; g_Xnv[i] = nv; }
    } else {
        int idx = (b - 2048) * 256 + tid;
        int t = idx >= 32 * N;
        int j = idx - t * 32 * N;
        int n = j / N, k = j - n * N;
        float v = (t ? Z1 : Z0)[(size_t)k * 32 + n];
        (t ? g_Zth1 : g_Zth0)[j] = __float2half_rn(v);
    }
}

// -------------------- Lambda = kXX_inv @ Z (cp.async fp32 staging) ----------
#define LA_SZ (128 * 68)            // fp32 A tile + pad
#define LZ_SZ (32 * 36)             // fp16x2 Z tile words
#define LAMBDA_SMEM ((2 * LA_SZ + 2 * LZ_SZ) * 4)

__global__ __launch_bounds__(256, 2) void lambda_hmma_kernel(
    const float* __restrict__ A0, const float* __restrict__ A1) {
    extern __shared__ float lsm[];
    float* sA = lsm;                               // [2][128*68] fp32
    uint32_t* sZ = (uint32_t*)(lsm + 2 * LA_SZ);   // [2][32*36]

    const int task = blockIdx.y, kh = blockIdx.z;
    const float* A = task ? A1 : A0;
    const __half* Zh = task ? g_Zth1 : g_Zth0;
    float* Lp = task ? (kh ? g_LpB1 : g_LpA1) : (kh ? g_LpB0 : g_LpA0);

    const int tid = threadIdx.x, lane = tid & 31, w = tid >> 5;
    const int t = lane & 3, qr = lane >> 2;
    const int rb = blockIdx.x * 128;
    const int kb0 = kh * (N / 2);

    auto stage = [&](int buf, int cb) {
        if (cb < 64) {
            const int k0 = kb0 + cb * 64;
            float* dA = sA + buf * LA_SZ;
            #pragma unroll
            for (int i = tid; i < 2048; i += 256) {
                int r = i >> 4, s = i & 15;
                cpasync16(s2u(dA + r * 68 + s * 4),
                          A + (size_t)(rb + r) * N + k0 + s * 4);
            }
            uint32_t* dZ = sZ + buf * LZ_SZ;
            {
                int n = tid >> 3, s = tid & 7;
                cpasync16(s2u(dZ + n * 36 + s * 4),
                          Zh + (size_t)n * N + k0 + s * 8);
            }
        }
        CP_COMMIT();
    };

    stage(0, 0);
    stage(1, 1);

    float zc[4][4];
    #pragma unroll
    for (int i = 0; i < 4; i++)
        #pragma unroll
        for (int j = 0; j < 4; j++) zc[i][j] = 0.f;

    const int row0 = w * 16 + qr;
    for (int cb = 0; cb < 64; cb++) {
        const int buf = cb & 1;
        CP_WAIT1();
        __syncthreads();
        const float* bA = sA + buf * LA_SZ;
        const uint32_t* bZ = sZ + buf * LZ_SZ;

        #pragma unroll
        for (int kt = 0; kt < 4; kt++) {
            const int kc = kt * 16 + 2 * t;
            const int kw = kt * 8 + t;
            uint32_t ah[4];
            float2 v0 = *(const float2*)&bA[row0 * 68 + kc];
            float2 v1 = *(const float2*)&bA[(row0 + 8) * 68 + kc];
            float2 v2 = *(const float2*)&bA[row0 * 68 + kc + 8];
            float2 v3 = *(const float2*)&bA[(row0 + 8) * 68 + kc + 8];
            ah[0] = packhf(v0.x, v0.y);
            ah[1] = packhf(v1.x, v1.y);
            ah[2] = packhf(v2.x, v2.y);
            ah[3] = packhf(v3.x, v3.y);
            #pragma unroll
            for (int nt = 0; nt < 4; nt++) {
                const int nc = nt * 8 + qr;
                mma_f16(zc[nt], ah, bZ[nc * 36 + kw], bZ[nc * 36 + kw + 4]);
            }
        }
        __syncthreads();
        stage(buf, cb + 2);
    }

    const int grow = rb + row0;
    #pragma unroll
    for (int nt = 0; nt < 4; nt++) {
        const int col = nt * 8 + 2 * t;
        Lp[(size_t)grow * 32 + col]           = zc[nt][0];
        Lp[(size_t)grow * 32 + col + 1]       = zc[nt][1];
        Lp[(size_t)(grow + 8) * 32 + col]     = zc[nt][2];
        Lp[(size_t)(grow + 8) * 32 + col + 1] = zc[nt][3];
    }
}

// Lambda partial sums -> transposed fp16 hi [32][N]
__global__ void lsplit_kernel() {
    int idx = blockIdx.x * blockDim.x + threadIdx.x;
    if (idx >= 2 * 32 * N) return;
    int t = idx >= 32 * N;
    int j = idx - t * 32 * N;
    int n = j / N, k = j - n * N;
    size_t src = (size_t)k * 32 + n;
    float v = (t ? g_LpA1 : g_LpA0)[src] + (t ? g_LpB1 : g_LpB0)[src];
    (t ? g_Lth1 : g_Lth0)[j] = __float2half_rn(v);
}

// -------------------- fused HMMA kernel (cp.async 2-stage + interleave) -----
template <int D>
__device__ void ftc(char* smraw, const __half* Xh,
                    const float* Qg, const __half* Lth,
                    const float* Xn, const float* Qn, float* Zg, int qb) {
    constexpr int QS = D + 8;
    constexpr int XSEG = D / 8;                    // 16B segs per X row
    __half* sQh  = (__half*)smraw;
    __half* sXhB = sQh + 128 * QS;                 // [4][64*QS]  (g*2+b)
    __half* sLhB = sXhB + 4 * 64 * QS;             // [4][32*72]
    float*  sXnB = (float*)(sLhB + 4 * 32 * 72);   // [4][64]
    float*  sRed = (float*)sXhB;                   // reused after chunk loop

    const int tid = threadIdx.x;
    const int g = tid >> 8, wtid = tid & 255;
    const int lane = tid & 31, w = wtid >> 5;
    const int t = lane & 3, qr = lane >> 2;
    const int wq0 = w * 16;
    __half* sXg = sXhB + (2 * g) * 64 * QS;
    __half* sLg = sLhB + (2 * g) * 32 * 72;
    float*  sXng = sXnB + (2 * g) * 64;

    // ldmatrix base addresses (buffer 0; add byte offset per buffer)
    const uint32_t aQ = s2u(sQh + (wq0 + (lane & 15)) * QS + ((lane >> 4) << 3));
    const uint32_t aX = s2u(sXg + ((lane & 7) + ((lane >> 4) << 3)) * QS +
                            (((lane >> 3) & 1) << 3));
    const uint32_t aL = s2u(sLg + ((lane & 7) + ((lane >> 4) << 3)) * 72 +
                            (((lane >> 3) & 1) << 3));

    // stage chunk -> buffer via cp.async (one commit group)
    auto stage = [&](int buf, int chunk) {
        const int xb = chunk * 64;
        __half* dX = sXg + buf * 64 * QS;
        #pragma unroll
        for (int i = wtid; i < 64 * XSEG; i += 256) {
            int r = i / XSEG, s = i - r * XSEG;
            cpasync16(s2u(dX + r * QS + s * 8), Xh + (size_t)(xb + r) * D + s * 8);
        }
        __half* dL = sLg + buf * 32 * 72;
        if (wtid < 256) {
            int n = wtid >> 3, s = wtid & 7;
            cpasync16(s2u(dL + n * 72 + s * 8), Lth + (size_t)n * N + xb + s * 8);
        }
        if (wtid < 16)
            cpasync16(s2u(sXng + buf * 64 + wtid * 4), Xn + xb + wtid * 4);
        CP_COMMIT();
    };

    // Q -> SMEM fp16 hi (all 512 threads)
    for (int i = tid; i < 128 * D; i += 512) {
        int r = i / D, c = i - r * D;
        sQh[r * QS + c] = __float2half_rn(Qg[(size_t)(qb + r) * D + c]);
    }
    // prologue: stage chunks for it=0 and it=1
    stage(0, g);
    stage(1, 2 + g);
    __syncthreads();
    const float qn0 = Qn[qb + wq0 + qr];
    const float qn1 = Qn[qb + wq0 + qr + 8];

    float zc[4][4];
    #pragma unroll
    for (int i = 0; i < 4; i++)
        #pragma unroll
        for (int j = 0; j < 4; j++) zc[i][j] = 0.f;

    for (int it = 0; it < 64; it++) {
        const int buf = it & 1;
        CP_WAIT1();
        GBAR(g);
        const uint32_t aXb = aX + buf * (64 * QS * 2);
        const uint32_t aLb = aL + buf * (32 * 72 * 2);
        const float* xn = sXng + buf * 64;

        // ---- phase 1: D1[16q x 64x] = Qh . Xh^T ----
        float c1[8][4];
        #pragma unroll
        for (int i = 0; i < 8; i++)
            #pragma unroll
            for (int j = 0; j < 4; j++) c1[i][j] = 0.f;

        #pragma unroll
        for (int kt = 0; kt < D / 16; kt++) {
            uint32_t ah[4];
            ldsm4(ah, aQ + kt * 32);
            #pragma unroll
            for (int np = 0; np < 4; np++) {
                uint32_t b[4];
                ldsm4(b, aXb + np * (16 * QS * 2) + kt * 32);
                mma_f16(c1[2 * np],     ah, b[0], b[1]);
                mma_f16(c1[2 * np + 1], ah, b[2], b[3]);
            }
        }

        // ---- epilogue + phase 2 interleaved per kt2 ----
        #pragma unroll
        for (int kt2 = 0; kt2 < 4; kt2++) {
            uint32_t Ph[4];
            #pragma unroll
            for (int s = 0; s < 2; s++) {
                const int nt = 2 * kt2 + s;
                const int x0 = nt * 8 + 2 * t;
                float xna = xn[x0], xnb = xn[x0 + 1];
                float p0 = __expf(-0.0078125f * (qn0 + xna - 2.f * c1[nt][0]));
                float p1 = __expf(-0.0078125f * (qn0 + xnb - 2.f * c1[nt][1]));
                float p2 = __expf(-0.0078125f * (qn1 + xna - 2.f * c1[nt][2]));
                float p3 = __expf(-0.0078125f * (qn1 + xnb - 2.f * c1[nt][3]));
                Ph[2 * s]     = packhf(p0, p1);
                Ph[2 * s + 1] = packhf(p2, p3);
            }
            #pragma unroll
            for (int np = 0; np < 2; np++) {
                uint32_t b[4];
                ldsm4(b, aLb + np * (16 * 72 * 2) + kt2 * 32);
                mma_f16(zc[2 * np],     Ph, b[0], b[1]);
                mma_f16(zc[2 * np + 1], Ph, b[2], b[3]);
            }
        }
        GBAR(g);

        if (it < 62) stage(buf, 2 * (it + 2) + g);
        else CP_COMMIT();                    // empty group keeps wait_group math
    }

    // ---- combine the two x-half partial sums (full-CTA sync) ----
    __syncthreads();
    const int row0 = wq0 + qr;
    if (g == 1) {
        #pragma unroll
        for (int nt = 0; nt < 4; nt++) {
            const int col = nt * 8 + 2 * t;
            sRed[row0 * 33 + col]           = zc[nt][0];
            sRed[row0 * 33 + col + 1]       = zc[nt][1];
            sRed[(row0 + 8) * 33 + col]     = zc[nt][2];
            sRed[(row0 + 8) * 33 + col + 1] = zc[nt][3];
        }
    }
    __syncthreads();
    if (g == 0) {
        #pragma unroll
        for (int nt = 0; nt < 4; nt++) {
            const int col = nt * 8 + 2 * t;
            float v0 = zc[nt][0] + sRed[row0 * 33 + col];
            float v1 = zc[nt][1] + sRed[row0 * 33 + col + 1];
            float v2 = zc[nt][2] + sRed[(row0 + 8) * 33 + col];
            float v3 = zc[nt][3] + sRed[(row0 + 8) * 33 + col + 1];
            Zg[(size_t)(qb + row0) * 32 + col]           = v0;
            Zg[(size_t)(qb + row0) * 32 + col + 1]       = v1;
            Zg[(size_t)(qb + row0 + 8) * 32 + col]       = v2;
            Zg[(size_t)(qb + row0 + 8) * 32 + col + 1]   = v3;
        }
    }
}

// D=96: (128*104 + 4*64*104 + 4*32*72) half + 4*64 f32 + red slack
#define FUSED_SMEM ((128 * 104 + 4 * 64 * 104 + 4 * 32 * 72) * 2 + 4 * 64 * 4 + 256)

__global__ __launch_bounds__(512, 1) void fusedtc_kernel() {
    extern __shared__ char sm[];
    int task = blockIdx.x >> 6;
    int qb   = (blockIdx.x & 63) * 128;
    if (task == 0)
        ftc<64>(sm, g_Xmh, g_xqm, g_Lth0, g_Xnm, g_qnm, g_zm, qb);
    else
        ftc<96>(sm, g_Xvh, g_xqv, g_Lth1, g_Xnv, g_qnv, g_zv, qb);
}

// -------------------- combine ----------------------------------------------
__global__ void combine_kernel(const float* __restrict__ y_mean,
                               const float* __restrict__ y_var,
                               float* __restrict__ out) {
    int i = blockIdx.x * blockDim.x + threadIdx.x;
    if (i < N * 32)
        out[i] = (y_mean[i] + g_zm[i]) + (y_var[i] + g_zv[i]);
}

// -------------------- launch ------------------------------------------------
extern "C" void kernel_launch(void* const* d_in, const int* in_sizes, int n_in,
                              void* d_out, int out_size) {
    const float* x_mu   = (const float*)d_in[0];
    const float* y_eta  = (const float*)d_in[1];
    const float* y_mean = (const float*)d_in[2];
    const float* y_var  = (const float*)d_in[3];
    const float* X_mean = (const float*)d_in[4];
    const float* X_var  = (const float*)d_in[5];
    const float* Z_mean = (const float*)d_in[6];
    const float* Z_var  = (const float*)d_in[7];
    const float* kMi    = (const float*)d_in[8];
    const float* kVi    = (const float*)d_in[9];
    float* out = (float*)d_out;

    cudaFuncSetAttribute(fusedtc_kernel,
                         cudaFuncAttributeMaxDynamicSharedMemorySize, FUSED_SMEM);
    cudaFuncSetAttribute(lambda_hmma_kernel,
                         cudaFuncAttributeMaxDynamicSharedMemorySize, LAMBDA_SMEM);

    prep_all_kernel<<<4096, 256>>>(x_mu, y_eta, y_mean, y_var,
                                   X_mean, X_var, Z_mean, Z_var);
    lambda_hmma_kernel<<<dim3(64, 2, 2), 256, LAMBDA_SMEM>>>(kMi, kVi);
    lsplit_kernel<<<(2 * 32 * N + 255) / 256, 256>>>();
    fusedtc_kernel<<<128, 512, FUSED_SMEM>>>();
    combine_kernel<<<(N * 32 + 255) / 256, 256>>>(y_mean, y_var, out);
}

// round 16
// speedup vs baseline: 1.1092x; 1.1092x over previous
#include <cuda_runtime.h>
#include <cuda_fp16.h>
#include <cstdint>

#define N 8192

// -------------------- device scratch ---------------------------------------
__device__ float g_xqm[N * 64];
__device__ float g_xqv[N * 96];
__device__ float g_qnm[N], g_qnv[N];
__device__ __align__(16) float g_Xnm[N];
__device__ __align__(16) float g_Xnv[N];
__device__ float g_LpA0[N * 32], g_LpB0[N * 32];   // Lambda partials (k-halves)
__device__ float g_LpA1[N * 32], g_LpB1[N * 32];
__device__ float g_zmA[N * 32], g_zmB[N * 32];     // z partials (x-halves)
__device__ float g_zvA[N * 32], g_zvB[N * 32];
__device__ __align__(16) __half g_Xmh[N * 64];
__device__ __align__(16) __half g_Xvh[N * 96];
__device__ __align__(16) __half g_Lth0[32 * N];
__device__ __align__(16) __half g_Lth1[32 * N];
__device__ __align__(16) __half g_Zth0[32 * N];
__device__ __align__(16) __half g_Zth1[32 * N];

// -------------------- mma / ldmatrix / cp.async helpers ---------------------
__device__ __forceinline__ void mma_f16(float c[4], const uint32_t a[4],
                                        uint32_t b0, uint32_t b1) {
    asm volatile(
        "mma.sync.aligned.m16n8k16.row.col.f32.f16.f16.f32 "
        "{%0,%1,%2,%3}, {%4,%5,%6,%7}, {%8,%9}, {%0,%1,%2,%3};"
        : "+f"(c[0]), "+f"(c[1]), "+f"(c[2]), "+f"(c[3])
        : "r"(a[0]), "r"(a[1]), "r"(a[2]), "r"(a[3]), "r"(b0), "r"(b1));
}
__device__ __forceinline__ uint32_t packhf(float lo, float hi) {
    uint32_t r;
    asm("cvt.rn.f16x2.f32 %0, %1, %2;" : "=r"(r) : "f"(hi), "f"(lo));
    return r;
}
__device__ __forceinline__ uint32_t s2u(const void* p) {
    return (uint32_t)__cvta_generic_to_shared(p);
}
__device__ __forceinline__ void ldsm4(uint32_t* r, uint32_t addr) {
    asm volatile("ldmatrix.sync.aligned.m8n8.x4.shared.b16 {%0,%1,%2,%3}, [%4];"
                 : "=r"(r[0]), "=r"(r[1]), "=r"(r[2]), "=r"(r[3]) : "r"(addr));
}
__device__ __forceinline__ void cpasync16(uint32_t dst, const void* src) {
    asm volatile("cp.async.cg.shared.global [%0], [%1], 16;"
                 :: "r"(dst), "l"(src) : "memory");
}
#define CP_COMMIT() asm volatile("cp.async.commit_group;" ::: "memory")
#define CP_WAIT1()  asm volatile("cp.async.wait_group 1;" ::: "memory")
#define GBAR(id) asm volatile("bar.sync %0, 256;" :: "r"(id) : "memory")

// -------------------- merged prep kernel ------------------------------------
__global__ void prep_all_kernel(const float* __restrict__ x_mu,
                                const float* __restrict__ y_eta,
                                const float* __restrict__ y_mean,
                                const float* __restrict__ y_var,
                                const float* __restrict__ Xm,
                                const float* __restrict__ Xv,
                                const float* __restrict__ Z0,
                                const float* __restrict__ Z1) {
    int b = blockIdx.x;
    int tid = threadIdx.x;
    if (b < 1024) {
        int q = (b * 256 + tid) >> 5;
        int lane = tid & 31;
        float a = x_mu[q * 32 + lane];
        float m = y_mean[q * 32 + lane] + y_var[q * 32 + lane];
        float e = 0.01f * y_eta[(N - 1 - q) * 32 + lane];
        g_xqm[q * 64 + lane] = a;       g_xqm[q * 64 + 32 + lane] = m;
        g_xqv[q * 96 + lane] = a;       g_xqv[q * 96 + 32 + lane] = e;
        g_xqv[q * 96 + 64 + lane] = m;
        float nm = a * a + m * m, nv = nm + e * e;
        #pragma unroll
        for (int o = 16; o; o >>= 1) {
            nm += __shfl_xor_sync(0xffffffffu, nm, o);
            nv += __shfl_xor_sync(0xffffffffu, nv, o);
        }
        if (lane == 0) { g_qnm[q] = nm; g_qnv[q] = nv; }
    } else if (b < 2048) {
        int i = ((b - 1024) * 256 + tid) >> 5;
        int lane = tid & 31;
        float nm = 0.f, nv = 0.f;
        #pragma unroll
        for (int c = 0; c < 64; c += 32) {
            float v = Xm[(size_t)i * 64 + c + lane];
            nm += v * v;
            g_Xmh[(size_t)i * 64 + c + lane] = __float2half_rn(v);
        }
        #pragma unroll
        for (int c = 0; c < 96; c += 32) {
            float v = Xv[(size_t)i * 96 + c + lane];
            nv += v * v;
            g_Xvh[(size_t)i * 96 + c + lane] = __float2half_rn(v);
        }
        #pragma unroll
        for (int o = 16; o; o >>= 1) {
            nm += __shfl_xor_sync(0xffffffffu, nm, o);
            nv += __shfl_xor_sync(0xffffffffu, nv, o);
        }
        if (lane == 0) { g_Xnm[i] = nm; g_Xnv[i] = nv; }
    } else {
        int idx = (b - 2048) * 256 + tid;
        int t = idx >= 32 * N;
        int j = idx - t * 32 * N;
        int n = j / N, k = j - n * N;
        float v = (t ? Z1 : Z0)[(size_t)k * 32 + n];
        (t ? g_Zth1 : g_Zth0)[j] = __float2half_rn(v);
    }
}

// -------------------- Lambda = kXX_inv @ Z on HMMA (R14 version) ------------
__global__ __launch_bounds__(256, 2) void lambda_hmma_kernel(
    const float* __restrict__ A0, const float* __restrict__ A1) {
    const int task = blockIdx.y, kh = blockIdx.z;
    const float* A = task ? A1 : A0;
    const __half* Zh = task ? g_Zth1 : g_Zth0;
    float* Lp = task ? (kh ? g_LpB1 : g_LpA1) : (kh ? g_LpB0 : g_LpA0);

    __shared__ __align__(16) uint32_t sAh[128 * 36];
    __shared__ __align__(16) uint32_t sZh[32 * 36];

    const int tid = threadIdx.x, lane = tid & 31, w = tid >> 5;
    const int t = lane & 3, qr = lane >> 2;
    const int rb = blockIdx.x * 128;
    const int kb0 = kh * (N / 2);
    const int zn = (tid * 4) >> 5, zw4 = (tid * 4) & 31;

    float4 pa[8];
    uint4 pzh;
    #pragma unroll
    for (int it = 0; it < 8; it++) {
        int idx = tid + it * 256;
        int r = idx >> 4, c4 = idx & 15;
        pa[it] = *(const float4*)&A[(size_t)(rb + r) * N + kb0 + c4 * 4];
    }
    pzh = ((const uint4*)Zh)[(zn * (N / 2) + kb0 / 2 + zw4) >> 2];

    float zc[4][4];
    #pragma unroll
    for (int i = 0; i < 4; i++)
        #pragma unroll
        for (int j = 0; j < 4; j++) zc[i][j] = 0.f;

    for (int cb = 0; cb < 64; cb++) {
        __syncthreads();
        #pragma unroll
        for (int it = 0; it < 8; it++) {
            int idx = tid + it * 256;
            int r = idx >> 4, c4 = idx & 15;
            float4 v = pa[it];
            *(uint2*)&sAh[r * 36 + c4 * 2] =
                make_uint2(packhf(v.x, v.y), packhf(v.z, v.w));
        }
        *(uint4*)&sZh[zn * 36 + zw4] = pzh;
        __syncthreads();

        if (cb < 63) {
            const int ko = kb0 + (cb + 1) * 64;
            #pragma unroll
            for (int it = 0; it < 8; it++) {
                int idx = tid + it * 256;
                int r = idx >> 4, c4 = idx & 15;
                pa[it] = *(const float4*)&A[(size_t)(rb + r) * N + ko + c4 * 4];
            }
            pzh = ((const uint4*)Zh)[(zn * (N / 2) + ko / 2 + zw4) >> 2];
        }

        #pragma unroll
        for (int kt = 0; kt < 4; kt++) {
            const int kw = kt * 8 + t;
            uint32_t ah[4];
            ah[0] = sAh[(w * 16 + qr) * 36 + kw];
            ah[1] = sAh[(w * 16 + qr + 8) * 36 + kw];
            ah[2] = sAh[(w * 16 + qr) * 36 + kw + 4];
            ah[3] = sAh[(w * 16 + qr + 8) * 36 + kw + 4];
            #pragma unroll
            for (int nt = 0; nt < 4; nt++) {
                const int nc = nt * 8 + qr;
                mma_f16(zc[nt], ah, sZh[nc * 36 + kw], sZh[nc * 36 + kw + 4]);
            }
        }
    }

    const int row0 = rb + w * 16 + qr;
    #pragma unroll
    for (int nt = 0; nt < 4; nt++) {
        const int col = nt * 8 + 2 * t;
        Lp[(size_t)row0 * 32 + col]           = zc[nt][0];
        Lp[(size_t)row0 * 32 + col + 1]       = zc[nt][1];
        Lp[(size_t)(row0 + 8) * 32 + col]     = zc[nt][2];
        Lp[(size_t)(row0 + 8) * 32 + col + 1] = zc[nt][3];
    }
}

// Lambda partial sums -> transposed fp16 hi [32][N]
__global__ void lsplit_kernel() {
    int idx = blockIdx.x * blockDim.x + threadIdx.x;
    if (idx >= 2 * 32 * N) return;
    int t = idx >= 32 * N;
    int j = idx - t * 32 * N;
    int n = j / N, k = j - n * N;
    size_t src = (size_t)k * 32 + n;
    float v = (t ? g_LpA1 : g_LpA0)[src] + (t ? g_LpB1 : g_LpB0)[src];
    (t ? g_Lth1 : g_Lth0)[j] = __float2half_rn(v);
}

// -------------------- fused HMMA (task-mixed groups, partial z) -------------
// CTA b: q-tile b&63, x-half b>>6. Group 0 runs task0 (D=64), group 1 task1
// (D=96). Each group: 256 threads, private smem carve, group-scoped barrier.
template <int D>
__device__ void ftc(char* gbase, int barid, const __half* Xh,
                    const float* Qg, const __half* Lth,
                    const float* Xn, const float* Qn, float* Zp,
                    int qb, int xh, int wtid) {
    constexpr int QS = D + 8;
    constexpr int XSEG = D / 8;
    __half* sQh  = (__half*)gbase;                 // 128*QS
    __half* sXhB = sQh + 128 * QS;                 // [2][64*QS]
    __half* sLhB = sXhB + 2 * 64 * QS;             // [2][32*72]
    float*  sXnB = (float*)(sLhB + 2 * 32 * 72);   // [2][64]

    const int lane = wtid & 31, w = wtid >> 5;
    const int t = lane & 3, qr = lane >> 2;
    const int wq0 = w * 16;
    const int cb0 = xh * 64;                       // first chunk of this half

    const uint32_t aQ = s2u(sQh + (wq0 + (lane & 15)) * QS + ((lane >> 4) << 3));
    const uint32_t aX = s2u(sXhB + ((lane & 7) + ((lane >> 4) << 3)) * QS +
                            (((lane >> 3) & 1) << 3));
    const uint32_t aL = s2u(sLhB + ((lane & 7) + ((lane >> 4) << 3)) * 72 +
                            (((lane >> 3) & 1) << 3));

    auto stage = [&](int buf, int it) {
        const int xb = (cb0 + it) * 64;
        __half* dX = sXhB + buf * 64 * QS;
        #pragma unroll
        for (int i = wtid; i < 64 * XSEG; i += 256) {
            int r = i / XSEG, s = i - r * XSEG;
            cpasync16(s2u(dX + r * QS + s * 8), Xh + (size_t)(xb + r) * D + s * 8);
        }
        __half* dL = sLhB + buf * 32 * 72;
        {
            int n = wtid >> 3, s = wtid & 7;
            cpasync16(s2u(dL + n * 72 + s * 8), Lth + (size_t)n * N + xb + s * 8);
        }
        if (wtid < 16)
            cpasync16(s2u(sXnB + buf * 64 + wtid * 4), Xn + xb + wtid * 4);
        CP_COMMIT();
    };

    for (int i = wtid; i < 128 * D; i += 256) {
        int r = i / D, c = i - r * D;
        sQh[r * QS + c] = __float2half_rn(Qg[(size_t)(qb + r) * D + c]);
    }
    stage(0, 0);
    stage(1, 1);
    GBAR(barid);
    const float qn0 = Qn[qb + wq0 + qr];
    const float qn1 = Qn[qb + wq0 + qr + 8];

    float zc[4][4];
    #pragma unroll
    for (int i = 0; i < 4; i++)
        #pragma unroll
        for (int j = 0; j < 4; j++) zc[i][j] = 0.f;

    for (int it = 0; it < 64; it++) {
        const int buf = it & 1;
        CP_WAIT1();
        GBAR(barid);
        const uint32_t aXb = aX + buf * (64 * QS * 2);
        const uint32_t aLb = aL + buf * (32 * 72 * 2);
        const float* xn = sXnB + buf * 64;

        float c1[8][4];
        #pragma unroll
        for (int i = 0; i < 8; i++)
            #pragma unroll
            for (int j = 0; j < 4; j++) c1[i][j] = 0.f;

        #pragma unroll
        for (int kt = 0; kt < D / 16; kt++) {
            uint32_t ah[4];
            ldsm4(ah, aQ + kt * 32);
            #pragma unroll
            for (int np = 0; np < 4; np++) {
                uint32_t b[4];
                ldsm4(b, aXb + np * (16 * QS * 2) + kt * 32);
                mma_f16(c1[2 * np],     ah, b[0], b[1]);
                mma_f16(c1[2 * np + 1], ah, b[2], b[3]);
            }
        }

        #pragma unroll
        for (int kt2 = 0; kt2 < 4; kt2++) {
            uint32_t Ph[4];
            #pragma unroll
            for (int s = 0; s < 2; s++) {
                const int nt = 2 * kt2 + s;
                const int x0 = nt * 8 + 2 * t;
                float xna = xn[x0], xnb = xn[x0 + 1];
                float p0 = __expf(-0.0078125f * (qn0 + xna - 2.f * c1[nt][0]));
                float p1 = __expf(-0.0078125f * (qn0 + xnb - 2.f * c1[nt][1]));
                float p2 = __expf(-0.0078125f * (qn1 + xna - 2.f * c1[nt][2]));
                float p3 = __expf(-0.0078125f * (qn1 + xnb - 2.f * c1[nt][3]));
                Ph[2 * s]     = packhf(p0, p1);
                Ph[2 * s + 1] = packhf(p2, p3);
            }
            #pragma unroll
            for (int np = 0; np < 2; np++) {
                uint32_t b[4];
                ldsm4(b, aLb + np * (16 * 72 * 2) + kt2 * 32);
                mma_f16(zc[2 * np],     Ph, b[0], b[1]);
                mma_f16(zc[2 * np + 1], Ph, b[2], b[3]);
            }
        }
        GBAR(barid);

        if (it < 62) stage(buf, it + 2);
        else CP_COMMIT();
    }

    // write this half's partial z (no cross-group reduction)
    const int row0 = qb + wq0 + qr;
    #pragma unroll
    for (int nt = 0; nt < 4; nt++) {
        const int col = nt * 8 + 2 * t;
        Zp[(size_t)row0 * 32 + col]           = zc[nt][0];
        Zp[(size_t)row0 * 32 + col + 1]       = zc[nt][1];
        Zp[(size_t)(row0 + 8) * 32 + col]     = zc[nt][2];
        Zp[(size_t)(row0 + 8) * 32 + col + 1] = zc[nt][3];
    }
}

// smem: group0 (D=64): (128*72 + 2*64*72 + 2*32*72)*2 + 2*64*4 = 46592
//       group1 (D=96): (128*104 + 2*64*104 + 2*32*72)*2 + 2*64*4 = 62976
#define G0_SMEM 46592
#define FUSED_SMEM (46592 + 62976)

__global__ __launch_bounds__(512, 1) void fusedtc_kernel() {
    extern __shared__ char sm[];
    int qb = (blockIdx.x & 63) * 128;
    int xh = blockIdx.x >> 6;
    int g  = threadIdx.x >> 8;
    int wtid = threadIdx.x & 255;
    if (g == 0)
        ftc<64>(sm, 1, g_Xmh, g_xqm, g_Lth0, g_Xnm, g_qnm,
                xh ? g_zmB : g_zmA, qb, xh, wtid);
    else
        ftc<96>(sm + G0_SMEM, 2, g_Xvh, g_xqv, g_Lth1, g_Xnv, g_qnv,
                xh ? g_zvB : g_zvA, qb, xh, wtid);
}

// -------------------- combine ----------------------------------------------
__global__ void combine_kernel(const float* __restrict__ y_mean,
                               const float* __restrict__ y_var,
                               float* __restrict__ out) {
    int i = blockIdx.x * blockDim.x + threadIdx.x;
    if (i < N * 32)
        out[i] = (y_mean[i] + (g_zmA[i] + g_zmB[i])) +
                 (y_var[i]  + (g_zvA[i] + g_zvB[i]));
}

// -------------------- launch ------------------------------------------------
extern "C" void kernel_launch(void* const* d_in, const int* in_sizes, int n_in,
                              void* d_out, int out_size) {
    const float* x_mu   = (const float*)d_in[0];
    const float* y_eta  = (const float*)d_in[1];
    const float* y_mean = (const float*)d_in[2];
    const float* y_var  = (const float*)d_in[3];
    const float* X_mean = (const float*)d_in[4];
    const float* X_var  = (const float*)d_in[5];
    const float* Z_mean = (const float*)d_in[6];
    const float* Z_var  = (const float*)d_in[7];
    const float* kMi    = (const float*)d_in[8];
    const float* kVi    = (const float*)d_in[9];
    float* out = (float*)d_out;

    cudaFuncSetAttribute(fusedtc_kernel,
                         cudaFuncAttributeMaxDynamicSharedMemorySize, FUSED_SMEM);

    prep_all_kernel<<<4096, 256>>>(x_mu, y_eta, y_mean, y_var,
                                   X_mean, X_var, Z_mean, Z_var);
    lambda_hmma_kernel<<<dim3(64, 2, 2), 256>>>(kMi, kVi);
    lsplit_kernel<<<(2 * 32 * N + 255) / 256, 256>>>();
    fusedtc_kernel<<<128, 512, FUSED_SMEM>>>();
    combine_kernel<<<(N * 32 + 255) / 256, 256>>>(y_mean, y_var, out);
}

// round 17
// speedup vs baseline: 1.2188x; 1.0988x over previous
#include <cuda_runtime.h>
#include <cuda_fp16.h>
#include <cstdint>

#define N 8192
// log2(e)/128 and log2(e)/64
#define C_LG2E_128 0.01127098895f
#define C_LG2E_64  0.02254197790f

// -------------------- device scratch ---------------------------------------
__device__ float g_xqm[N * 64];
__device__ float g_xqv[N * 96];
__device__ float g_qnm[N], g_qnv[N];               // SCALED: -|q|^2*log2e/128
__device__ __align__(16) float g_Xnm[N];           // SCALED: -|x|^2*log2e/128
__device__ __align__(16) float g_Xnv[N];
__device__ float g_LpA0[N * 32], g_LpB0[N * 32];   // Lambda partials (k-halves)
__device__ float g_LpA1[N * 32], g_LpB1[N * 32];
__device__ float g_zmA[N * 32], g_zmB[N * 32];     // z partials (x-halves)
__device__ float g_zvA[N * 32], g_zvB[N * 32];
__device__ __align__(16) __half g_Xmh[N * 64];
__device__ __align__(16) __half g_Xvh[N * 96];
__device__ __align__(16) __half g_Lth0[32 * N];
__device__ __align__(16) __half g_Lth1[32 * N];
__device__ __align__(16) __half g_Zth0[32 * N];
__device__ __align__(16) __half g_Zth1[32 * N];

// -------------------- helpers -----------------------------------------------
__device__ __forceinline__ void mma_f16(float c[4], const uint32_t a[4],
                                        uint32_t b0, uint32_t b1) {
    asm volatile(
        "mma.sync.aligned.m16n8k16.row.col.f32.f16.f16.f32 "
        "{%0,%1,%2,%3}, {%4,%5,%6,%7}, {%8,%9}, {%0,%1,%2,%3};"
        : "+f"(c[0]), "+f"(c[1]), "+f"(c[2]), "+f"(c[3])
        : "r"(a[0]), "r"(a[1]), "r"(a[2]), "r"(a[3]), "r"(b0), "r"(b1));
}
__device__ __forceinline__ uint32_t packhf(float lo, float hi) {
    uint32_t r;
    asm("cvt.rn.f16x2.f32 %0, %1, %2;" : "=r"(r) : "f"(hi), "f"(lo));
    return r;
}
__device__ __forceinline__ float ex2f(float x) {
    float r;
    asm("ex2.approx.f32 %0, %1;" : "=f"(r) : "f"(x));
    return r;
}
__device__ __forceinline__ uint32_t s2u(const void* p) {
    return (uint32_t)__cvta_generic_to_shared(p);
}
__device__ __forceinline__ void ldsm4(uint32_t* r, uint32_t addr) {
    asm volatile("ldmatrix.sync.aligned.m8n8.x4.shared.b16 {%0,%1,%2,%3}, [%4];"
                 : "=r"(r[0]), "=r"(r[1]), "=r"(r[2]), "=r"(r[3]) : "r"(addr));
}
__device__ __forceinline__ void cpasync16(uint32_t dst, const void* src) {
    asm volatile("cp.async.cg.shared.global [%0], [%1], 16;"
                 :: "r"(dst), "l"(src) : "memory");
}
#define CP_COMMIT() asm volatile("cp.async.commit_group;" ::: "memory")
#define CP_WAIT1()  asm volatile("cp.async.wait_group 1;" ::: "memory")
#define GBAR(id) asm volatile("bar.sync %0, 256;" :: "r"(id) : "memory")

// -------------------- merged prep kernel ------------------------------------
__global__ void prep_all_kernel(const float* __restrict__ x_mu,
                                const float* __restrict__ y_eta,
                                const float* __restrict__ y_mean,
                                const float* __restrict__ y_var,
                                const float* __restrict__ Xm,
                                const float* __restrict__ Xv,
                                const float* __restrict__ Z0,
                                const float* __restrict__ Z1) {
    int b = blockIdx.x;
    int tid = threadIdx.x;
    if (b < 1024) {
        int q = (b * 256 + tid) >> 5;
        int lane = tid & 31;
        float a = x_mu[q * 32 + lane];
        float m = y_mean[q * 32 + lane] + y_var[q * 32 + lane];
        float e = 0.01f * y_eta[(N - 1 - q) * 32 + lane];
        g_xqm[q * 64 + lane] = a;       g_xqm[q * 64 + 32 + lane] = m;
        g_xqv[q * 96 + lane] = a;       g_xqv[q * 96 + 32 + lane] = e;
        g_xqv[q * 96 + 64 + lane] = m;
        float nm = a * a + m * m, nv = nm + e * e;
        #pragma unroll
        for (int o = 16; o; o >>= 1) {
            nm += __shfl_xor_sync(0xffffffffu, nm, o);
            nv += __shfl_xor_sync(0xffffffffu, nv, o);
        }
        if (lane == 0) {
            g_qnm[q] = -nm * C_LG2E_128;
            g_qnv[q] = -nv * C_LG2E_128;
        }
    } else if (b < 2048) {
        int i = ((b - 1024) * 256 + tid) >> 5;
        int lane = tid & 31;
        float nm = 0.f, nv = 0.f;
        #pragma unroll
        for (int c = 0; c < 64; c += 32) {
            float v = Xm[(size_t)i * 64 + c + lane];
            nm += v * v;
            g_Xmh[(size_t)i * 64 + c + lane] = __float2half_rn(v);
        }
        #pragma unroll
        for (int c = 0; c < 96; c += 32) {
            float v = Xv[(size_t)i * 96 + c + lane];
            nv += v * v;
            g_Xvh[(size_t)i * 96 + c + lane] = __float2half_rn(v);
        }
        #pragma unroll
        for (int o = 16; o; o >>= 1) {
            nm += __shfl_xor_sync(0xffffffffu, nm, o);
            nv += __shfl_xor_sync(0xffffffffu, nv, o);
        }
        if (lane == 0) {
            g_Xnm[i] = -nm * C_LG2E_128;
            g_Xnv[i] = -nv * C_LG2E_128;
        }
    } else {
        int idx = (b - 2048) * 256 + tid;
        int t = idx >= 32 * N;
        int j = idx - t * 32 * N;
        int n = j / N, k = j - n * N;
        float v = (t ? Z1 : Z0)[(size_t)k * 32 + n];
        (t ? g_Zth1 : g_Zth0)[j] = __float2half_rn(v);
    }
}

// -------------------- Lambda = kXX_inv @ Z on HMMA (R14 version) ------------
__global__ __launch_bounds__(256, 2) void lambda_hmma_kernel(
    const float* __restrict__ A0, const float* __restrict__ A1) {
    const int task = blockIdx.y, kh = blockIdx.z;
    const float* A = task ? A1 : A0;
    const __half* Zh = task ? g_Zth1 : g_Zth0;
    float* Lp = task ? (kh ? g_LpB1 : g_LpA1) : (kh ? g_LpB0 : g_LpA0);

    __shared__ __align__(16) uint32_t sAh[128 * 36];
    __shared__ __align__(16) uint32_t sZh[32 * 36];

    const int tid = threadIdx.x, lane = tid & 31, w = tid >> 5;
    const int t = lane & 3, qr = lane >> 2;
    const int rb = blockIdx.x * 128;
    const int kb0 = kh * (N / 2);
    const int zn = (tid * 4) >> 5, zw4 = (tid * 4) & 31;

    float4 pa[8];
    uint4 pzh;
    #pragma unroll
    for (int it = 0; it < 8; it++) {
        int idx = tid + it * 256;
        int r = idx >> 4, c4 = idx & 15;
        pa[it] = *(const float4*)&A[(size_t)(rb + r) * N + kb0 + c4 * 4];
    }
    pzh = ((const uint4*)Zh)[(zn * (N / 2) + kb0 / 2 + zw4) >> 2];

    float zc[4][4];
    #pragma unroll
    for (int i = 0; i < 4; i++)
        #pragma unroll
        for (int j = 0; j < 4; j++) zc[i][j] = 0.f;

    for (int cb = 0; cb < 64; cb++) {
        __syncthreads();
        #pragma unroll
        for (int it = 0; it < 8; it++) {
            int idx = tid + it * 256;
            int r = idx >> 4, c4 = idx & 15;
            float4 v = pa[it];
            *(uint2*)&sAh[r * 36 + c4 * 2] =
                make_uint2(packhf(v.x, v.y), packhf(v.z, v.w));
        }
        *(uint4*)&sZh[zn * 36 + zw4] = pzh;
        __syncthreads();

        if (cb < 63) {
            const int ko = kb0 + (cb + 1) * 64;
            #pragma unroll
            for (int it = 0; it < 8; it++) {
                int idx = tid + it * 256;
                int r = idx >> 4, c4 = idx & 15;
                pa[it] = *(const float4*)&A[(size_t)(rb + r) * N + ko + c4 * 4];
            }
            pzh = ((const uint4*)Zh)[(zn * (N / 2) + ko / 2 + zw4) >> 2];
        }

        #pragma unroll
        for (int kt = 0; kt < 4; kt++) {
            const int kw = kt * 8 + t;
            uint32_t ah[4];
            ah[0] = sAh[(w * 16 + qr) * 36 + kw];
            ah[1] = sAh[(w * 16 + qr + 8) * 36 + kw];
            ah[2] = sAh[(w * 16 + qr) * 36 + kw + 4];
            ah[3] = sAh[(w * 16 + qr + 8) * 36 + kw + 4];
            #pragma unroll
            for (int nt = 0; nt < 4; nt++) {
                const int nc = nt * 8 + qr;
                mma_f16(zc[nt], ah, sZh[nc * 36 + kw], sZh[nc * 36 + kw + 4]);
            }
        }
    }

    const int row0 = rb + w * 16 + qr;
    #pragma unroll
    for (int nt = 0; nt < 4; nt++) {
        const int col = nt * 8 + 2 * t;
        Lp[(size_t)row0 * 32 + col]           = zc[nt][0];
        Lp[(size_t)row0 * 32 + col + 1]       = zc[nt][1];
        Lp[(size_t)(row0 + 8) * 32 + col]     = zc[nt][2];
        Lp[(size_t)(row0 + 8) * 32 + col + 1] = zc[nt][3];
    }
}

// -------- Lambda partials -> transposed fp16 (coalesced tile transpose) -----
// Block: 256 threads, handles 256 k x 32 n for one task.
__global__ void lsplit_kernel() {
    __shared__ float tile[256][33];
    const int task = blockIdx.x >> 5;
    const int kb = (blockIdx.x & 31) * 256;
    const int tid = threadIdx.x;
    const float* LA = task ? g_LpA1 : g_LpA0;
    const float* LB = task ? g_LpB1 : g_LpB0;
    __half* Lt = task ? g_Lth1 : g_Lth0;

    const int n = tid & 31, kr = tid >> 5;     // 8 k-rows per pass
    #pragma unroll
    for (int p = 0; p < 32; p++) {
        int k = kr + p * 8;
        size_t src = (size_t)(kb + k) * 32 + n;
        tile[k][n] = LA[src] + LB[src];
    }
    __syncthreads();
    // write: thread covers n = tid>>3, k-range (tid&7)*32 .. +32 (64B contiguous)
    const int wn = tid >> 3, wk = (tid & 7) * 32;
    __half* dst = Lt + (size_t)wn * N + kb + wk;
    #pragma unroll
    for (int i = 0; i < 32; i += 8) {
        uint4 v;
        __half h[8];
        #pragma unroll
        for (int j = 0; j < 8; j++) h[j] = __float2half_rn(tile[wk + i + j][wn]);
        v = *(uint4*)h;
        *(uint4*)(dst + i) = v;
    }
}

// -------------------- fused HMMA (3-stage cp.async, ex2 epilogue) -----------
template <int D>
__device__ void ftc(char* gbase, int barid, const __half* Xh,
                    const float* Qg, const __half* Lth,
                    const float* Xn, const float* Qn, float* Zp,
                    int qb, int xh, int wtid) {
    constexpr int QS = D + 8;
    constexpr int XSEG = D / 8;
    __half* sQh  = (__half*)gbase;                 // 128*QS
    __half* sXhB = sQh + 128 * QS;                 // [3][64*QS]
    __half* sLhB = sXhB + 3 * 64 * QS;             // [3][32*72]
    float*  sXnB = (float*)(sLhB + 3 * 32 * 72);   // [3][64]

    const int lane = wtid & 31, w = wtid >> 5;
    const int t = lane & 3, qr = lane >> 2;
    const int wq0 = w * 16;
    const int cb0 = xh * 64;

    const uint32_t aQ = s2u(sQh + (wq0 + (lane & 15)) * QS + ((lane >> 4) << 3));
    const uint32_t aX = s2u(sXhB + ((lane & 7) + ((lane >> 4) << 3)) * QS +
                            (((lane >> 3) & 1) << 3));
    const uint32_t aL = s2u(sLhB + ((lane & 7) + ((lane >> 4) << 3)) * 72 +
                            (((lane >> 3) & 1) << 3));

    auto stage = [&](int buf, int it) {
        const int xb = (cb0 + it) * 64;
        __half* dX = sXhB + buf * 64 * QS;
        #pragma unroll
        for (int i = wtid; i < 64 * XSEG; i += 256) {
            int r = i / XSEG, s = i - r * XSEG;
            cpasync16(s2u(dX + r * QS + s * 8), Xh + (size_t)(xb + r) * D + s * 8);
        }
        __half* dL = sLhB + buf * 32 * 72;
        {
            int n = wtid >> 3, s = wtid & 7;
            cpasync16(s2u(dL + n * 72 + s * 8), Lth + (size_t)n * N + xb + s * 8);
        }
        if (wtid < 16)
            cpasync16(s2u(sXnB + buf * 64 + wtid * 4), Xn + xb + wtid * 4);
        CP_COMMIT();
    };

    for (int i = wtid; i < 128 * D; i += 256) {
        int r = i / D, c = i - r * D;
        sQh[r * QS + c] = __float2half_rn(Qg[(size_t)(qb + r) * D + c]);
    }
    stage(0, 0);
    stage(1, 1);
    const float qn0 = Qn[qb + wq0 + qr];           // pre-scaled
    const float qn1 = Qn[qb + wq0 + qr + 8];

    float zc[4][4];
    #pragma unroll
    for (int i = 0; i < 4; i++)
        #pragma unroll
        for (int j = 0; j < 4; j++) zc[i][j] = 0.f;

    int bufc = 0, bufs = 2;
    for (int it = 0; it < 64; it++) {
        CP_WAIT1();
        GBAR(barid);
        const uint32_t aXb = aX + bufc * (64 * QS * 2);
        const uint32_t aLb = aL + bufc * (32 * 72 * 2);
        const float* xn = sXnB + bufc * 64;

        float c1[8][4];
        #pragma unroll
        for (int i = 0; i < 8; i++)
            #pragma unroll
            for (int j = 0; j < 4; j++) c1[i][j] = 0.f;

        #pragma unroll
        for (int kt = 0; kt < D / 16; kt++) {
            uint32_t ah[4];
            ldsm4(ah, aQ + kt * 32);
            #pragma unroll
            for (int np = 0; np < 4; np++) {
                uint32_t b[4];
                ldsm4(b, aXb + np * (16 * QS * 2) + kt * 32);
                mma_f16(c1[2 * np],     ah, b[0], b[1]);
                mma_f16(c1[2 * np + 1], ah, b[2], b[3]);
            }
        }

        #pragma unroll
        for (int kt2 = 0; kt2 < 4; kt2++) {
            uint32_t Ph[4];
            #pragma unroll
            for (int s = 0; s < 2; s++) {
                const int nt = 2 * kt2 + s;
                const int x0 = nt * 8 + 2 * t;
                float sa0 = qn0 + xn[x0], sb0 = qn0 + xn[x0 + 1];
                float sa1 = qn1 + xn[x0], sb1 = qn1 + xn[x0 + 1];
                float p0 = ex2f(fmaf(c1[nt][0], C_LG2E_64, sa0));
                float p1 = ex2f(fmaf(c1[nt][1], C_LG2E_64, sb0));
                float p2 = ex2f(fmaf(c1[nt][2], C_LG2E_64, sa1));
                float p3 = ex2f(fmaf(c1[nt][3], C_LG2E_64, sb1));
                Ph[2 * s]     = packhf(p0, p1);
                Ph[2 * s + 1] = packhf(p2, p3);
            }
            #pragma unroll
            for (int np = 0; np < 2; np++) {
                uint32_t b[4];
                ldsm4(b, aLb + np * (16 * 72 * 2) + kt2 * 32);
                mma_f16(zc[2 * np],     Ph, b[0], b[1]);
                mma_f16(zc[2 * np + 1], Ph, b[2], b[3]);
            }
        }

        if (it < 62) stage(bufs, it + 2);
        else CP_COMMIT();
        bufc = (bufc == 2) ? 0 : bufc + 1;
        bufs = (bufs == 2) ? 0 : bufs + 1;
    }

    const int row0 = qb + wq0 + qr;
    #pragma unroll
    for (int nt = 0; nt < 4; nt++) {
        const int col = nt * 8 + 2 * t;
        Zp[(size_t)row0 * 32 + col]           = zc[nt][0];
        Zp[(size_t)row0 * 32 + col + 1]       = zc[nt][1];
        Zp[(size_t)(row0 + 8) * 32 + col]     = zc[nt][2];
        Zp[(size_t)(row0 + 8) * 32 + col + 1] = zc[nt][3];
    }
}

// smem: group0 (D=64): (128*72 + 3*64*72 + 3*32*72)*2 + 3*64*4 = 60672
//       group1 (D=96): (128*104 + 3*64*104 + 3*32*72)*2 + 3*64*4 = 81152
#define G0_SMEM 60672
#define FUSED_SMEM (60672 + 81152)

__global__ __launch_bounds__(512, 1) void fusedtc_kernel() {
    extern __shared__ char sm[];
    int qb = (blockIdx.x & 63) * 128;
    int xh = blockIdx.x >> 6;
    int g  = threadIdx.x >> 8;
    int wtid = threadIdx.x & 255;
    if (g == 0)
        ftc<64>(sm, 1, g_Xmh, g_xqm, g_Lth0, g_Xnm, g_qnm,
                xh ? g_zmB : g_zmA, qb, xh, wtid);
    else
        ftc<96>(sm + G0_SMEM, 2, g_Xvh, g_xqv, g_Lth1, g_Xnv, g_qnv,
                xh ? g_zvB : g_zvA, qb, xh, wtid);
}

// -------------------- combine ----------------------------------------------
__global__ void combine_kernel(const float* __restrict__ y_mean,
                               const float* __restrict__ y_var,
                               float* __restrict__ out) {
    int i = blockIdx.x * blockDim.x + threadIdx.x;
    if (i < N * 32)
        out[i] = (y_mean[i] + (g_zmA[i] + g_zmB[i])) +
                 (y_var[i]  + (g_zvA[i] + g_zvB[i]));
}

// -------------------- launch ------------------------------------------------
extern "C" void kernel_launch(void* const* d_in, const int* in_sizes, int n_in,
                              void* d_out, int out_size) {
    const float* x_mu   = (const float*)d_in[0];
    const float* y_eta  = (const float*)d_in[1];
    const float* y_mean = (const float*)d_in[2];
    const float* y_var  = (const float*)d_in[3];
    const float* X_mean = (const float*)d_in[4];
    const float* X_var  = (const float*)d_in[5];
    const float* Z_mean = (const float*)d_in[6];
    const float* Z_var  = (const float*)d_in[7];
    const float* kMi    = (const float*)d_in[8];
    const float* kVi    = (const float*)d_in[9];
    float* out = (float*)d_out;

    cudaFuncSetAttribute(fusedtc_kernel,
                         cudaFuncAttributeMaxDynamicSharedMemorySize, FUSED_SMEM);

    prep_all_kernel<<<4096, 256>>>(x_mu, y_eta, y_mean, y_var,
                                   X_mean, X_var, Z_mean, Z_var);
    lambda_hmma_kernel<<<dim3(64, 2, 2), 256>>>(kMi, kVi);
    lsplit_kernel<<<64, 256>>>();
    fusedtc_kernel<<<128, 512, FUSED_SMEM>>>();
    combine_kernel<<<(N * 32 + 255) / 256, 256>>>(y_mean, y_var, out);
}